// round 3
// baseline (speedup 1.0000x reference)
#include <cuda_runtime.h>
#include <math.h>
#include <float.h>

#define OUTD    12
#define N_VOX   1728              // 12*12*12
#define N_ROIS  128
#define N_PTS   160000
#define NCH     64
#define KMAX    64                // cap on points per (roi,voxel); fallback handles overflow
#define NRV     (N_ROIS * N_VOX)  // 221184

// N_PTS must be an exact multiple of the build block size: every warp is full,
// so __ballot_sync(0xffffffff, ...) in the ROI loop is safe.
static_assert(N_PTS % 256 == 0, "build kernel assumes full warps");

// Scratch (__device__ globals = sanctioned scratch; zero-initialized at load).
// d_count is self-cleaned by pool_kernel each run -> no zeroing kernel needed.
__device__ int d_count[NRV];
__device__ int d_list[NRV * KMAX];

// ---------------------------------------------------------------------------
// Kernel 1: one thread per point, warp-uniform loop over all 128 ROIs
// (params staged in smem, broadcast LDS.128). Circle quick-reject made
// WARP-UNIFORM via ballot: the skip branch (94% of iters) never diverges.
// ---------------------------------------------------------------------------
__global__ __launch_bounds__(256) void build_lists_kernel(
    const float* __restrict__ rois, const float* __restrict__ pts)
{
    __shared__ float4 sA[N_ROIS];  // {cx, cy, r2_margin, cz}
    __shared__ float4 sB[N_ROIS];  // {cosa, sina, hdx, hdy}
    __shared__ float4 sC[N_ROIS];  // {hdz, vx, vy, vz}

    int t = threadIdx.x;
    if (t < N_ROIS) {
        const float* R = rois + t * 7;
        float cx = R[0], cy = R[1], cz = R[2];
        float dx = R[3], dy = R[4], dz = R[5];
        float ry = R[6];
        float hdx = dx * 0.5f, hdy = dy * 0.5f, hdz = dz * 0.5f;
        float r2  = (hdx * hdx + hdy * hdy) * 1.0002f + 1e-6f;  // conservative
        float ca  = cosf(-ry), sa = sinf(-ry);
        sA[t] = make_float4(cx, cy, r2, cz);
        sB[t] = make_float4(ca, sa, hdx, hdy);
        sC[t] = make_float4(hdz, dx / (float)OUTD, dy / (float)OUTD, dz / (float)OUTD);
    }
    __syncthreads();

    int p = blockIdx.x * blockDim.x + t;      // always < N_PTS (exact grid)
    float px = pts[3 * p + 0];
    float py = pts[3 * p + 1];
    float pz = pts[3 * p + 2];

    #pragma unroll 4
    for (int r = 0; r < N_ROIS; r++) {
        float4 A = sA[r];                     // broadcast LDS.128 (uniform r)
        float sx = px - A.x;
        float sy = py - A.y;
        float d2 = sx * sx + sy * sy;
        bool cand = (d2 <= A.z);
        // warp-uniform skip: no divergence on the 94% all-miss iterations
        if (__ballot_sync(0xffffffffu, cand) == 0u) continue;
        if (!cand) continue;                  // rare divergent tail below

        float sz = pz - A.w;
        float4 B = sB[r];
        float4 C = sC[r];
        float lx = sx * B.x - sy * B.y;       // rotate into roi frame (angle = -ry)
        float ly = sx * B.y + sy * B.x;
        // exact replication of the reference predicate
        bool in_box = (lx > -B.z) && (lx < B.z) &&
                      (ly > -B.w) && (ly < B.w) &&
                      (fabsf(sz - C.x) <= C.x);
        if (!in_box) continue;

        int xi = min(OUTD - 1, max(0, (int)floorf((lx + B.z) / C.y)));
        int yi = min(OUTD - 1, max(0, (int)floorf((ly + B.w) / C.z)));
        int zi = min(OUTD - 1, max(0, (int)floorf(sz / C.w)));
        int rv = r * N_VOX + xi * (OUTD * OUTD) + yi * OUTD + zi;
        int c = atomicAdd(&d_count[rv], 1);
        if (c < KMAX) d_list[rv * KMAX + c] = p;
    }
}

// ---------------------------------------------------------------------------
// Kernel 2: one warp per (roi,voxel). Lane handles 2 channels (float2).
// Self-cleans d_count (restores the zero invariant for the next replay).
// Empty voxel (92%) -> 256B coalesced zero write; else max over <=KMAX
// coalesced 256B feature rows. Overflow -> full-rescan correctness fallback.
// ---------------------------------------------------------------------------
__global__ __launch_bounds__(256) void pool_kernel(
    const float* __restrict__ rois, const float* __restrict__ pts,
    const float* __restrict__ feat, float* __restrict__ out)
{
    int gtid = blockIdx.x * blockDim.x + threadIdx.x;
    int warp = gtid >> 5;
    int lane = threadIdx.x & 31;
    if (warp >= NRV) return;

    int n = d_count[warp];
    if (lane == 0) d_count[warp] = 0;   // self-clean for next graph replay

    float2* o = (float2*)(out + (size_t)warp * NCH);
    if (n == 0) {
        o[lane] = make_float2(0.f, 0.f);
        return;
    }

    float mx0 = -FLT_MAX, mx1 = -FLT_MAX;
    int m = min(n, KMAX);
    const int* lst = &d_list[warp * KMAX];
    for (int j = 0; j < m; j++) {
        int pid = lst[j];                                     // warp-uniform load
        float2 v = ((const float2*)(feat + (size_t)pid * NCH))[lane];
        mx0 = fmaxf(mx0, v.x);
        mx1 = fmaxf(mx1, v.y);
    }

    if (n > KMAX) {
        // Correctness fallback (statistically never taken): rescan all points.
        int r = warp / N_VOX, vox = warp % N_VOX;
        int xi = vox / (OUTD * OUTD), yi = (vox / OUTD) % OUTD, zi = vox % OUTD;
        const float* R = rois + r * 7;
        float cx = R[0], cy = R[1], cz = R[2];
        float dx = R[3], dy = R[4], dz = R[5];
        float ry = R[6];
        float hdx = dx * 0.5f, hdy = dy * 0.5f, hdz = dz * 0.5f;
        float ca = cosf(-ry), sa = sinf(-ry);
        float vx = dx / (float)OUTD, vy = dy / (float)OUTD, vz = dz / (float)OUTD;
        for (int base = 0; base < N_PTS; base += 32) {
            int p = base + lane;
            bool hit = false;
            if (p < N_PTS) {
                float sx = pts[3 * p + 0] - cx;
                float sy = pts[3 * p + 1] - cy;
                float sz = pts[3 * p + 2] - cz;
                float lx = sx * ca - sy * sa;
                float ly = sx * sa + sy * ca;
                if ((lx > -hdx) && (lx < hdx) && (ly > -hdy) && (ly < hdy) &&
                    (fabsf(sz - hdz) <= hdz)) {
                    int xa = min(OUTD - 1, max(0, (int)floorf((lx + hdx) / vx)));
                    int ya = min(OUTD - 1, max(0, (int)floorf((ly + hdy) / vy)));
                    int za = min(OUTD - 1, max(0, (int)floorf(sz / vz)));
                    hit = (xa == xi) && (ya == yi) && (za == zi);
                }
            }
            unsigned mask = __ballot_sync(0xffffffffu, hit);
            while (mask) {
                int src = __ffs(mask) - 1;
                mask &= mask - 1;
                int pid = base + src;
                float2 v = ((const float2*)(feat + (size_t)pid * NCH))[lane];
                mx0 = fmaxf(mx0, v.x);
                mx1 = fmaxf(mx1, v.y);
            }
        }
    }
    o[lane] = make_float2(mx0, mx1);
}

// ---------------------------------------------------------------------------
extern "C" void kernel_launch(void* const* d_in, const int* in_sizes, int n_in,
                              void* d_out, int out_size)
{
    const float* rois = (const float*)d_in[0];       // (128, 7)
    const float* pts  = (const float*)d_in[1];       // (160000, 3)
    const float* feat = (const float*)d_in[2];       // (160000, 64)
    float* out = (float*)d_out;                      // (128, 12, 12, 12, 64)

    build_lists_kernel<<<N_PTS / 256, 256>>>(rois, pts);
    pool_kernel<<<NRV / 8, 256>>>(rois, pts, feat, out);  // 1 warp per (roi,voxel)
}

// round 4
// speedup vs baseline: 2.1623x; 2.1623x over previous
#include <cuda_runtime.h>
#include <math.h>
#include <float.h>

#define OUTD    12
#define N_VOX   1728              // 12*12*12
#define N_ROIS  128
#define N_PTS   160000
#define NCH     64
#define KMAX    64                // cap on points per (roi,voxel); fallback handles overflow
#define NRV     (N_ROIS * N_VOX)  // 221184 = 864 * 256

static_assert(N_PTS % 256 == 0, "exact build grid");
static_assert(NRV % 256 == 0, "exact pool grid");

// Scratch (__device__ globals = sanctioned scratch; zero-initialized at load).
// d_count is self-cleaned by pool_kernel each run -> invariant holds across replays.
__device__ int d_count[NRV];
__device__ __align__(16) int d_list[NRV * KMAX];   // 16B align for int4 loads

// ---------------------------------------------------------------------------
// Kernel 1: one thread per point, warp-uniform loop over all 128 ROIs
// (params staged in smem, broadcast LDS.128). Plain predicated quick-reject
// (R1 form — the ballot variant regressed).
// ---------------------------------------------------------------------------
__global__ __launch_bounds__(256) void build_lists_kernel(
    const float* __restrict__ rois, const float* __restrict__ pts)
{
    __shared__ float4 sA[N_ROIS];  // {cx, cy, r2_margin, cz}
    __shared__ float4 sB[N_ROIS];  // {cosa, sina, hdx, hdy}
    __shared__ float4 sC[N_ROIS];  // {hdz, vx, vy, vz}

    int t = threadIdx.x;
    if (t < N_ROIS) {
        const float* R = rois + t * 7;
        float cx = R[0], cy = R[1], cz = R[2];
        float dx = R[3], dy = R[4], dz = R[5];
        float ry = R[6];
        float hdx = dx * 0.5f, hdy = dy * 0.5f, hdz = dz * 0.5f;
        float r2  = (hdx * hdx + hdy * hdy) * 1.0002f + 1e-6f;  // conservative
        float ca  = cosf(-ry), sa = sinf(-ry);
        sA[t] = make_float4(cx, cy, r2, cz);
        sB[t] = make_float4(ca, sa, hdx, hdy);
        sC[t] = make_float4(hdz, dx / (float)OUTD, dy / (float)OUTD, dz / (float)OUTD);
    }
    __syncthreads();

    int p = blockIdx.x * blockDim.x + t;      // always < N_PTS (exact grid)
    float px = pts[3 * p + 0];
    float py = pts[3 * p + 1];
    float pz = pts[3 * p + 2];

    #pragma unroll 4
    for (int r = 0; r < N_ROIS; r++) {
        float4 A = sA[r];                     // broadcast LDS.128 (uniform r)
        float sx = px - A.x;
        float sy = py - A.y;
        float d2 = sx * sx + sy * sy;
        if (d2 > A.z) continue;               // ~99.8% rejected here

        float sz = pz - A.w;
        float4 B = sB[r];
        float4 C = sC[r];
        float lx = sx * B.x - sy * B.y;       // rotate into roi frame (angle = -ry)
        float ly = sx * B.y + sy * B.x;
        bool in_box = (lx > -B.z) && (lx < B.z) &&
                      (ly > -B.w) && (ly < B.w) &&
                      (fabsf(sz - C.x) <= C.x);
        if (!in_box) continue;

        int xi = min(OUTD - 1, max(0, (int)floorf((lx + B.z) / C.y)));
        int yi = min(OUTD - 1, max(0, (int)floorf((ly + B.w) / C.z)));
        int zi = min(OUTD - 1, max(0, (int)floorf(sz / C.w)));
        int rv = r * N_VOX + xi * (OUTD * OUTD) + yi * OUTD + zi;
        int c = atomicAdd(&d_count[rv], 1);
        if (c < KMAX) d_list[rv * KMAX + c] = p;
    }
}

// ---------------------------------------------------------------------------
// Kernel 2: block = 256 voxels (864 blocks = one wave). Counts loaded
// COALESCED into smem once (single scoreboard wait/block), self-cleaned
// coalesced. Each warp sweeps 32 voxels: count from smem (uniform -> no
// divergence), empty -> fire-and-forget 256B zero store; non-empty -> one
// int4 pid load + up to 4 independent (MLP) feature-row loads.
// ---------------------------------------------------------------------------
__global__ __launch_bounds__(256) void pool_kernel(
    const float* __restrict__ rois, const float* __restrict__ pts,
    const float* __restrict__ feat, float* __restrict__ out)
{
    __shared__ int sCnt[256];

    int t    = threadIdx.x;
    int lane = t & 31;
    int wid  = t >> 5;
    int vblock = blockIdx.x << 8;             // first voxel of this block

    // Coalesced count load + self-clean (restores zero invariant for replay).
    int myv = vblock + t;
    sCnt[t] = d_count[myv];
    d_count[myv] = 0;
    __syncthreads();

    int kbase = wid << 5;                     // this warp's 32 voxels (local)
    for (int k = 0; k < 32; k++) {
        int n  = sCnt[kbase + k];             // warp-uniform -> no divergence
        int gv = vblock + kbase + k;
        float2* o = (float2*)(out + (size_t)gv * NCH);

        if (n == 0) {
            o[lane] = make_float2(0.f, 0.f);  // fire-and-forget STG.64
            continue;
        }

        float mx0 = -FLT_MAX, mx1 = -FLT_MAX;
        const int* lst = &d_list[(size_t)gv * KMAX];

        // Fast path: first up-to-4 pids in one aligned int4, feature loads
        // issued unrolled & predicated -> independent, MLP=4.
        int4 p4 = *(const int4*)lst;
        int m = min(n, KMAX);
        {
            float2 v0, v1, v2, v3;
            if (m > 0) v0 = ((const float2*)(feat + (size_t)p4.x * NCH))[lane];
            if (m > 1) v1 = ((const float2*)(feat + (size_t)p4.y * NCH))[lane];
            if (m > 2) v2 = ((const float2*)(feat + (size_t)p4.z * NCH))[lane];
            if (m > 3) v3 = ((const float2*)(feat + (size_t)p4.w * NCH))[lane];
            if (m > 0) { mx0 = fmaxf(mx0, v0.x); mx1 = fmaxf(mx1, v0.y); }
            if (m > 1) { mx0 = fmaxf(mx0, v1.x); mx1 = fmaxf(mx1, v1.y); }
            if (m > 2) { mx0 = fmaxf(mx0, v2.x); mx1 = fmaxf(mx1, v2.y); }
            if (m > 3) { mx0 = fmaxf(mx0, v3.x); mx1 = fmaxf(mx1, v3.y); }
        }
        for (int j = 4; j < m; j++) {
            int pid = lst[j];
            float2 v = ((const float2*)(feat + (size_t)pid * NCH))[lane];
            mx0 = fmaxf(mx0, v.x);
            mx1 = fmaxf(mx1, v.y);
        }

        if (n > KMAX) {
            // Correctness fallback (statistically never taken): rescan all
            // points. n is warp-uniform so the whole warp enters together.
            int r = gv / N_VOX, vox = gv % N_VOX;
            int xi = vox / (OUTD * OUTD), yi = (vox / OUTD) % OUTD, zi = vox % OUTD;
            const float* R = rois + r * 7;
            float cx = R[0], cy = R[1], cz = R[2];
            float dx = R[3], dy = R[4], dz = R[5];
            float ry = R[6];
            float hdx = dx * 0.5f, hdy = dy * 0.5f, hdz = dz * 0.5f;
            float ca = cosf(-ry), sa = sinf(-ry);
            float vx = dx / (float)OUTD, vy = dy / (float)OUTD, vz = dz / (float)OUTD;
            for (int base = 0; base < N_PTS; base += 32) {
                int p = base + lane;
                bool hit = false;
                if (p < N_PTS) {
                    float sx = pts[3 * p + 0] - cx;
                    float sy = pts[3 * p + 1] - cy;
                    float szz = pts[3 * p + 2] - cz;
                    float lx = sx * ca - sy * sa;
                    float ly = sx * sa + sy * ca;
                    if ((lx > -hdx) && (lx < hdx) && (ly > -hdy) && (ly < hdy) &&
                        (fabsf(szz - hdz) <= hdz)) {
                        int xa = min(OUTD - 1, max(0, (int)floorf((lx + hdx) / vx)));
                        int ya = min(OUTD - 1, max(0, (int)floorf((ly + hdy) / vy)));
                        int za = min(OUTD - 1, max(0, (int)floorf(szz / vz)));
                        hit = (xa == xi) && (ya == yi) && (za == zi);
                    }
                }
                unsigned mask = __ballot_sync(0xffffffffu, hit);
                while (mask) {
                    int src = __ffs(mask) - 1;
                    mask &= mask - 1;
                    int pid = base + src;
                    float2 v = ((const float2*)(feat + (size_t)pid * NCH))[lane];
                    mx0 = fmaxf(mx0, v.x);
                    mx1 = fmaxf(mx1, v.y);
                }
            }
        }
        o[lane] = make_float2(mx0, mx1);
    }
}

// ---------------------------------------------------------------------------
extern "C" void kernel_launch(void* const* d_in, const int* in_sizes, int n_in,
                              void* d_out, int out_size)
{
    const float* rois = (const float*)d_in[0];       // (128, 7)
    const float* pts  = (const float*)d_in[1];       // (160000, 3)
    const float* feat = (const float*)d_in[2];       // (160000, 64)
    float* out = (float*)d_out;                      // (128, 12, 12, 12, 64)

    build_lists_kernel<<<N_PTS / 256, 256>>>(rois, pts);
    pool_kernel<<<NRV / 256, 256>>>(rois, pts, feat, out);  // 256 voxels/block, 1 wave
}

// round 5
// speedup vs baseline: 2.3021x; 1.0647x over previous
#include <cuda_runtime.h>
#include <math.h>
#include <float.h>

#define OUTD    12
#define N_VOX   1728              // 12*12*12
#define N_ROIS  128
#define N_PTS   160000
#define NCH     64
#define KMAX    64                // cap on points per (roi,voxel); fallback handles overflow
#define NRV     (N_ROIS * N_VOX)  // 221184 = 864 * 256
#define NF4     (NRV * NCH / 4)   // output as float4 count = 3,538,944

static_assert(N_PTS % 256 == 0, "exact build grid");
static_assert(NRV % 256 == 0, "exact pool grid");

// Scratch (__device__ globals = sanctioned scratch; zero-initialized at load).
// d_count is self-cleaned by pool_kernel each run -> invariant holds across replays.
__device__ int d_count[NRV];
__device__ __align__(16) int d_list[NRV * KMAX];   // 16B align for int4 loads

// ---------------------------------------------------------------------------
// Kernel 1: one thread per point, warp-uniform loop over all 128 ROIs.
// ALSO zero-fills the entire output (fire-and-forget STG.128): its LTS write
// traffic overlaps this kernel's compute, so pool never writes empty voxels.
// ---------------------------------------------------------------------------
__global__ __launch_bounds__(256) void build_lists_kernel(
    const float* __restrict__ rois, const float* __restrict__ pts,
    float* __restrict__ out)
{
    __shared__ float4 sA[N_ROIS];  // {cx, cy, r2_margin, cz}
    __shared__ float4 sB[N_ROIS];  // {cosa, sina, hdx, hdy}
    __shared__ float4 sC[N_ROIS];  // {hdz, vx, vy, vz}

    int t = threadIdx.x;
    int p = blockIdx.x * blockDim.x + t;      // always < N_PTS (exact grid)

    // Point load issued early (overlaps staging + zero-fill).
    float px = pts[3 * p + 0];
    float py = pts[3 * p + 1];
    float pz = pts[3 * p + 2];

    if (t < N_ROIS) {
        const float* R = rois + t * 7;
        float cx = R[0], cy = R[1], cz = R[2];
        float dx = R[3], dy = R[4], dz = R[5];
        float ry = R[6];
        float hdx = dx * 0.5f, hdy = dy * 0.5f, hdz = dz * 0.5f;
        float r2  = (hdx * hdx + hdy * hdy) * 1.0002f + 1e-6f;  // conservative
        float ca  = cosf(-ry), sa = sinf(-ry);
        sA[t] = make_float4(cx, cy, r2, cz);
        sB[t] = make_float4(ca, sa, hdx, hdy);
        sC[t] = make_float4(hdz, dx / (float)OUTD, dy / (float)OUTD, dz / (float)OUTD);
    }

    // Zero-fill whole output: ~22 coalesced fire-and-forget STG.128 per thread.
    {
        float4 z = make_float4(0.f, 0.f, 0.f, 0.f);
        float4* o4 = (float4*)out;
        for (int i = p; i < NF4; i += N_PTS) o4[i] = z;
    }
    __syncthreads();

    #pragma unroll 4
    for (int r = 0; r < N_ROIS; r++) {
        float4 A = sA[r];                     // broadcast LDS.128 (uniform r)
        float sx = px - A.x;
        float sy = py - A.y;
        float d2 = sx * sx + sy * sy;
        if (d2 > A.z) continue;               // ~99.8% rejected here

        float sz = pz - A.w;
        float4 B = sB[r];
        float4 C = sC[r];
        float lx = sx * B.x - sy * B.y;       // rotate into roi frame (angle = -ry)
        float ly = sx * B.y + sy * B.x;
        bool in_box = (lx > -B.z) && (lx < B.z) &&
                      (ly > -B.w) && (ly < B.w) &&
                      (fabsf(sz - C.x) <= C.x);
        if (!in_box) continue;

        int xi = min(OUTD - 1, max(0, (int)floorf((lx + B.z) / C.y)));
        int yi = min(OUTD - 1, max(0, (int)floorf((ly + B.w) / C.z)));
        int zi = min(OUTD - 1, max(0, (int)floorf(sz / C.w)));
        int rv = r * N_VOX + xi * (OUTD * OUTD) + yi * OUTD + zi;
        int c = atomicAdd(&d_count[rv], 1);
        if (c < KMAX) d_list[rv * KMAX + c] = p;
    }
}

// ---------------------------------------------------------------------------
// Kernel 2: block = 256 voxels (864 blocks = one wave). Coalesced count scan
// into smem (+ self-clean of dirty counts), ballot-compaction of non-empty
// voxels (~19/block) into a smem worklist, then the 8 warps process entries
// with a 2-deep software pipeline (next pid-int4 load issued before waiting
// on current feature loads). Empty voxels: NO work (zeros written by build).
// ---------------------------------------------------------------------------
__global__ __launch_bounds__(256) void pool_kernel(
    const float* __restrict__ rois, const float* __restrict__ pts,
    const float* __restrict__ feat, float* __restrict__ out)
{
    __shared__ int sCnt[256];
    __shared__ int sQ[256];
    __shared__ int sQn;

    int t    = threadIdx.x;
    int lane = t & 31;
    int wid  = t >> 5;
    int vblock = blockIdx.x << 8;             // first voxel of this block

    int c = d_count[vblock + t];              // coalesced 1KB burst
    sCnt[t] = c;
    if (c) d_count[vblock + t] = 0;           // self-clean only dirty entries
    if (t == 0) sQn = 0;
    __syncthreads();

    // Ballot-compact non-empty local voxel ids into sQ (order irrelevant).
    unsigned m = __ballot_sync(0xffffffffu, c > 0);
    int base = 0;
    if (lane == 0 && m) base = atomicAdd(&sQn, __popc(m));
    base = __shfl_sync(0xffffffffu, base, 0);
    if (c > 0) sQ[base + __popc(m & ((1u << lane) - 1u))] = t;
    __syncthreads();
    int qn = sQn;

    // Warps grab entries strided; 2-deep pipeline hides the list-load latency.
    int i = wid;
    int nGv = -1, nN = 0;
    int4 nP4 = make_int4(0, 0, 0, 0);
    if (i < qn) {
        int lv = sQ[i];
        nGv = vblock + lv;
        nN  = sCnt[lv];
        nP4 = *(const int4*)&d_list[(size_t)nGv * KMAX];
    }
    while (nGv >= 0) {
        int gv = nGv, n = nN;
        int4 p4 = nP4;
        i += 8;
        if (i < qn) {
            int lv = sQ[i];
            nGv = vblock + lv;
            nN  = sCnt[lv];
            nP4 = *(const int4*)&d_list[(size_t)nGv * KMAX];   // prefetch next
        } else {
            nGv = -1;
        }

        float mx0 = -FLT_MAX, mx1 = -FLT_MAX;
        int mm = min(n, KMAX);
        {   // up to 4 independent feature-row loads (MLP), predicated
            float2 v0, v1, v2, v3;
            if (mm > 0) v0 = ((const float2*)(feat + (size_t)p4.x * NCH))[lane];
            if (mm > 1) v1 = ((const float2*)(feat + (size_t)p4.y * NCH))[lane];
            if (mm > 2) v2 = ((const float2*)(feat + (size_t)p4.z * NCH))[lane];
            if (mm > 3) v3 = ((const float2*)(feat + (size_t)p4.w * NCH))[lane];
            if (mm > 0) { mx0 = fmaxf(mx0, v0.x); mx1 = fmaxf(mx1, v0.y); }
            if (mm > 1) { mx0 = fmaxf(mx0, v1.x); mx1 = fmaxf(mx1, v1.y); }
            if (mm > 2) { mx0 = fmaxf(mx0, v2.x); mx1 = fmaxf(mx1, v2.y); }
            if (mm > 3) { mx0 = fmaxf(mx0, v3.x); mx1 = fmaxf(mx1, v3.y); }
        }
        const int* lst = &d_list[(size_t)gv * KMAX];
        for (int j = 4; j < mm; j++) {        // rare (P(n>4) tiny)
            int pid = lst[j];
            float2 v = ((const float2*)(feat + (size_t)pid * NCH))[lane];
            mx0 = fmaxf(mx0, v.x);
            mx1 = fmaxf(mx1, v.y);
        }

        if (n > KMAX) {
            // Correctness fallback (statistically never taken): rescan all
            // points. n is warp-uniform so the whole warp enters together.
            int r = gv / N_VOX, vox = gv % N_VOX;
            int xi = vox / (OUTD * OUTD), yi = (vox / OUTD) % OUTD, zi = vox % OUTD;
            const float* R = rois + r * 7;
            float cx = R[0], cy = R[1], cz = R[2];
            float dx = R[3], dy = R[4], dz = R[5];
            float ry = R[6];
            float hdx = dx * 0.5f, hdy = dy * 0.5f, hdz = dz * 0.5f;
            float ca = cosf(-ry), sa = sinf(-ry);
            float vx = dx / (float)OUTD, vy = dy / (float)OUTD, vz = dz / (float)OUTD;
            for (int bb = 0; bb < N_PTS; bb += 32) {
                int pp = bb + lane;
                bool hit = false;
                {
                    float sx = pts[3 * pp + 0] - cx;
                    float sy = pts[3 * pp + 1] - cy;
                    float szz = pts[3 * pp + 2] - cz;
                    float lx = sx * ca - sy * sa;
                    float ly = sx * sa + sy * ca;
                    if ((lx > -hdx) && (lx < hdx) && (ly > -hdy) && (ly < hdy) &&
                        (fabsf(szz - hdz) <= hdz)) {
                        int xa = min(OUTD - 1, max(0, (int)floorf((lx + hdx) / vx)));
                        int ya = min(OUTD - 1, max(0, (int)floorf((ly + hdy) / vy)));
                        int za = min(OUTD - 1, max(0, (int)floorf(szz / vz)));
                        hit = (xa == xi) && (ya == yi) && (za == zi);
                    }
                }
                unsigned mk = __ballot_sync(0xffffffffu, hit);
                while (mk) {
                    int src = __ffs(mk) - 1;
                    mk &= mk - 1;
                    int pid = bb + src;
                    float2 v = ((const float2*)(feat + (size_t)pid * NCH))[lane];
                    mx0 = fmaxf(mx0, v.x);
                    mx1 = fmaxf(mx1, v.y);
                }
            }
        }

        float2* o = (float2*)(out + (size_t)gv * NCH);
        o[lane] = make_float2(mx0, mx1);
    }
}

// ---------------------------------------------------------------------------
extern "C" void kernel_launch(void* const* d_in, const int* in_sizes, int n_in,
                              void* d_out, int out_size)
{
    const float* rois = (const float*)d_in[0];       // (128, 7)
    const float* pts  = (const float*)d_in[1];       // (160000, 3)
    const float* feat = (const float*)d_in[2];       // (160000, 64)
    float* out = (float*)d_out;                      // (128, 12, 12, 12, 64)

    build_lists_kernel<<<N_PTS / 256, 256>>>(rois, pts, out);
    pool_kernel<<<NRV / 256, 256>>>(rois, pts, feat, out);  // 256 voxels/block
}